// round 15
// baseline (speedup 1.0000x reference)
#include <cuda_runtime.h>
#include <cuda_bf16.h>
#include <math.h>

// ---------------------------------------------------------------------------
// InstantNGP hash-grid embedding, 16 levels, F=2, T=2^19, 1M points.
//
// R15 = R12 (281.1us) with ILP-4 aux kernels. R12's profile showed
// scatter_kernel at issue=2.5%/occ=79% — pure ATOMG-latency bound (one
// 318-cyc atomic chain per thread). hist_kernel has the same shape. Fix:
// 4 points per thread => 4 independent atomic chains in flight per thread
// (exposed latency /4). Key stores/loads become uint4 (STG/LDG.128).
// Main embedding kernel, scan, zero: byte-identical to R12.
// ---------------------------------------------------------------------------

#define NLVL 16
#define LOG2_T 19
#define TABLE_SIZE (1u << LOG2_T)
#define HMASK (TABLE_SIZE - 1u)
#define BSZ 1048576
#define PRIME1 2654435761u
#define PRIME2 805459861u
#define TPB 256
#define GRID_RES 32               // 32^3 sort bins
#define NBINS (GRID_RES * GRID_RES * GRID_RES)

__device__ unsigned g_hist[NBINS];
__device__ unsigned g_keys[BSZ];
__device__ unsigned g_perm[BSZ];

struct LevelParams {
    float invgs;   // 1 / grid_size (host-computed via double)
    float resm1;   // (float)(res - 1)
};
struct AllParams {
    LevelParams lp[NLVL];
};

// ---- Morton key helpers ----------------------------------------------------
__device__ __forceinline__ unsigned expand3(unsigned v) {
    v &= 0x3FFu;
    v = (v | (v << 16)) & 0x030000FFu;
    v = (v | (v << 8))  & 0x0300F00Fu;
    v = (v | (v << 4))  & 0x030C30C3u;
    v = (v | (v << 2))  & 0x09249249u;
    return v;
}

__device__ __forceinline__ unsigned point_key(float x0, float x1, float x2) {
    unsigned c0 = (unsigned)fminf(fmaxf(floorf((x0 + 1.0f) * 16.0f), 0.0f), 31.0f);
    unsigned c1 = (unsigned)fminf(fmaxf(floorf((x1 + 1.0f) * 16.0f), 0.0f), 31.0f);
    unsigned c2 = (unsigned)fminf(fmaxf(floorf((x2 + 1.0f) * 16.0f), 0.0f), 31.0f);
    return expand3(c0) | (expand3(c1) << 1) | (expand3(c2) << 2);
}

// ---- K1: zero histogram ----------------------------------------------------
__global__ void zero_hist_kernel() {
    int i = blockIdx.x * blockDim.x + threadIdx.x;
    if (i < NBINS) g_hist[i] = 0u;
}

// ---- K2: histogram + key store, 4 points/thread (ILP for atomic latency) ---
__global__ __launch_bounds__(TPB)
void hist_kernel(const float* __restrict__ x) {
    const int t = blockIdx.x * TPB + threadIdx.x;   // 0 .. BSZ/4-1
    const int base = t * 4;

    // 4 points = 12 consecutive floats; three float4 loads (coalesced)
    const float4* __restrict__ x4 = (const float4*)x;
    const float4 a = __ldg(&x4[t * 3 + 0]);
    const float4 b = __ldg(&x4[t * 3 + 1]);
    const float4 c = __ldg(&x4[t * 3 + 2]);

    const unsigned k0 = point_key(a.x, a.y, a.z);
    const unsigned k1 = point_key(a.w, b.x, b.y);
    const unsigned k2 = point_key(b.z, b.w, c.x);
    const unsigned k3 = point_key(c.y, c.z, c.w);

    *(uint4*)&g_keys[base] = make_uint4(k0, k1, k2, k3);

    // 4 independent atomic chains in flight
    atomicAdd(&g_hist[k0], 1u);
    atomicAdd(&g_hist[k1], 1u);
    atomicAdd(&g_hist[k2], 1u);
    atomicAdd(&g_hist[k3], 1u);
}

// ---- K3: single-block exclusive scan over NBINS ----------------------------
__global__ __launch_bounds__(1024)
void scan_kernel() {
    __shared__ unsigned sums[1024];
    const int t = threadIdx.x;
    const int base = t * (NBINS / 1024);          // 32 bins per thread

    unsigned local[NBINS / 1024];
    unsigned run = 0;
#pragma unroll
    for (int j = 0; j < NBINS / 1024; ++j) {
        local[j] = run;
        run += g_hist[base + j];
    }
    sums[t] = run;
    __syncthreads();

    // Hillis-Steele inclusive scan (read before write each step)
    for (int off = 1; off < 1024; off <<= 1) {
        unsigned v = (t >= off) ? sums[t - off] : 0u;
        __syncthreads();
        sums[t] += v;
        __syncthreads();
    }
    const unsigned prefix = sums[t] - run;        // exclusive prefix of this chunk

#pragma unroll
    for (int j = 0; j < NBINS / 1024; ++j)
        g_hist[base + j] = prefix + local[j];
}

// ---- K4: scatter, 4 points/thread (ILP for atomic latency) -----------------
__global__ __launch_bounds__(TPB)
void scatter_kernel() {
    const int t = blockIdx.x * TPB + threadIdx.x;   // 0 .. BSZ/4-1
    const int base = t * 4;

    const uint4 k = *(const uint4*)&g_keys[base];

    // 4 independent atomic chains; stores depend only on their own chain
    const unsigned s0 = atomicAdd(&g_hist[k.x], 1u);
    const unsigned s1 = atomicAdd(&g_hist[k.y], 1u);
    const unsigned s2 = atomicAdd(&g_hist[k.z], 1u);
    const unsigned s3 = atomicAdd(&g_hist[k.w], 1u);

    g_perm[s0] = (unsigned)(base + 0);
    g_perm[s1] = (unsigned)(base + 1);
    g_perm[s2] = (unsigned)(base + 2);
    g_perm[s3] = (unsigned)(base + 3);
}

// ---- K5: main embedding kernel (byte-identical to R10/R12 winner) ----------
__global__ __launch_bounds__(TPB)
void hash_embed_kernel(const float* __restrict__ x,
                       const float* __restrict__ emb,
                       float* __restrict__ out,
                       AllParams P)
{
    const int i = blockIdx.x * TPB + threadIdx.x;   // BSZ % TPB == 0
    const unsigned p = g_perm[i];

    const float x0 = __ldg(&x[p * 3 + 0]);
    const float x1 = __ldg(&x[p * 3 + 1]);
    const float x2 = __ldg(&x[p * 3 + 2]);

    float2 r[NLVL];

#pragma unroll
    for (int l = 0; l < NLVL; ++l) {
        const float invgs = P.lp[l].invgs;
        const float rm1   = P.lp[l].resm1;

        const float rel0 = (x0 + 1.0f) * invgs;
        const float rel1 = (x1 + 1.0f) * invgs;
        const float rel2 = (x2 + 1.0f) * invgs;

        const float f0 = fminf(fmaxf(floorf(rel0), 0.0f), rm1);
        const float f1 = fminf(fmaxf(floorf(rel1), 0.0f), rm1);
        const float f2 = fminf(fmaxf(floorf(rel2), 0.0f), rm1);

        const float w0 = rel0 - f0;
        const float w1 = rel1 - f1;
        const float w2 = rel2 - f2;

        const unsigned u0 = (unsigned)f0;
        const unsigned u1 = (unsigned)f1;
        const unsigned u2 = (unsigned)f2;

        const bool odd0 = (u0 & 1u) != 0u;

        const unsigned a1 = u0 + 1u;
        const unsigned b0 = u1 * PRIME1;
        const unsigned b1 = b0 + PRIME1;
        const unsigned c0 = u2 * PRIME2;
        const unsigned c1 = c0 + PRIME2;

        const float2* __restrict__ tab =
            (const float2*)emb + (size_t)l * TABLE_SIZE;
        const float4* __restrict__ tab4 = (const float4*)tab;

        const unsigned h00 = (u0 ^ b0 ^ c0) & HMASK;
        const unsigned h10 = (u0 ^ b1 ^ c0) & HMASK;
        const unsigned h01 = (u0 ^ b0 ^ c1) & HMASK;
        const unsigned h11 = (u0 ^ b1 ^ c1) & HMASK;

        // 4 unconditional float4 pair-loads — independent, one round
        const float4 q00 = __ldg(&tab4[h00 >> 1]);
        const float4 q10 = __ldg(&tab4[h10 >> 1]);
        const float4 q01 = __ldg(&tab4[h01 >> 1]);
        const float4 q11 = __ldg(&tab4[h11 >> 1]);

        // 4 predicated float2 loads for odd u0 — same latency round
        float2 e00, e10, e01, e11;
        if (odd0) {
            e00 = __ldg(&tab[(a1 ^ b0 ^ c0) & HMASK]);
            e10 = __ldg(&tab[(a1 ^ b1 ^ c0) & HMASK]);
            e01 = __ldg(&tab[(a1 ^ b0 ^ c1) & HMASK]);
            e11 = __ldg(&tab[(a1 ^ b1 ^ c1) & HMASK]);
        } else {
            e00 = e10 = e01 = e11 = make_float2(0.0f, 0.0f);
        }

        const bool o00 = (h00 & 1u) != 0u;
        const bool o10 = (h10 & 1u) != 0u;
        const bool o01 = (h01 & 1u) != 0u;
        const bool o11 = (h11 & 1u) != 0u;

        const float2 vA00 = o00 ? make_float2(q00.z, q00.w) : make_float2(q00.x, q00.y);
        const float2 vA10 = o10 ? make_float2(q10.z, q10.w) : make_float2(q10.x, q10.y);
        const float2 vA01 = o01 ? make_float2(q01.z, q01.w) : make_float2(q01.x, q01.y);
        const float2 vA11 = o11 ? make_float2(q11.z, q11.w) : make_float2(q11.x, q11.y);

        const float2 vB00 = odd0 ? e00 : (o00 ? make_float2(q00.x, q00.y) : make_float2(q00.z, q00.w));
        const float2 vB10 = odd0 ? e10 : (o10 ? make_float2(q10.x, q10.y) : make_float2(q10.z, q10.w));
        const float2 vB01 = odd0 ? e01 : (o01 ? make_float2(q01.x, q01.y) : make_float2(q01.z, q01.w));
        const float2 vB11 = odd0 ? e11 : (o11 ? make_float2(q11.x, q11.y) : make_float2(q11.z, q11.w));

        const float m0 = 1.0f - w0;
        const float m1 = 1.0f - w1;
        const float m2 = 1.0f - w2;

        const float p00 = m1 * m2;
        const float p10 = w1 * m2;
        const float p01 = m1 * w2;
        const float p11 = w1 * w2;

        const float cx00x = fmaf(w0, vB00.x, m0 * vA00.x);
        const float cx00y = fmaf(w0, vB00.y, m0 * vA00.y);
        const float cx10x = fmaf(w0, vB10.x, m0 * vA10.x);
        const float cx10y = fmaf(w0, vB10.y, m0 * vA10.y);
        const float cx01x = fmaf(w0, vB01.x, m0 * vA01.x);
        const float cx01y = fmaf(w0, vB01.y, m0 * vA01.y);
        const float cx11x = fmaf(w0, vB11.x, m0 * vA11.x);
        const float cx11y = fmaf(w0, vB11.y, m0 * vA11.y);

        float accx = p00 * cx00x;
        float accy = p00 * cx00y;
        accx = fmaf(p10, cx10x, accx);
        accy = fmaf(p10, cx10y, accy);
        accx = fmaf(p01, cx01x, accx);
        accy = fmaf(p01, cx01y, accy);
        accx = fmaf(p11, cx11x, accx);
        accy = fmaf(p11, cx11y, accy);

        r[l].x = accx;
        r[l].y = accy;

        __syncthreads();   // per-level phase-locking (known-good)
    }

    // direct per-thread output (R6 tail)
    float4* __restrict__ o = (float4*)(out + (size_t)p * 32);
#pragma unroll
    for (int k = 0; k < 8; ++k) {
        o[k] = make_float4(r[2 * k].x, r[2 * k].y,
                           r[2 * k + 1].x, r[2 * k + 1].y);
    }
}

extern "C" void kernel_launch(void* const* d_in, const int* in_sizes, int n_in,
                              void* d_out, int out_size)
{
    const float* x   = (const float*)d_in[0];   // (1048576, 3) f32
    const float* emb = (const float*)d_in[1];   // (16, 524288, 2) f32
    float* out = (float*)d_out;                 // (1048576, 32) f32

    // Recompute RESOLUTIONS with the reference's double-precision formula
    // (several floor() results sit exactly on integer boundaries).
    AllParams P;
    const double growth = exp((log(512.0) - log(16.0)) / 15.0);
    for (int i = 0; i < NLVL; ++i) {
        int res = (int)floor(16.0 * pow(growth, (double)i));
        float gsf = (float)(2.0 / (double)res);
        P.lp[i].invgs = (float)(1.0 / (double)gsf);
        P.lp[i].resm1 = (float)(res - 1);
    }

    // sort pipeline (recomputed every call — graph replays re-run all of it)
    zero_hist_kernel<<<(NBINS + 1023) / 1024, 1024>>>();
    hist_kernel<<<BSZ / (TPB * 4), TPB>>>(x);
    scan_kernel<<<1, 1024>>>();
    scatter_kernel<<<BSZ / (TPB * 4), TPB>>>();
    hash_embed_kernel<<<BSZ / TPB, TPB>>>(x, emb, out, P);
}